// round 8
// baseline (speedup 1.0000x reference)
#include <cuda_runtime.h>
#include <cuda_bf16.h>
#include <math.h>
#include <stdint.h>

#define SEQ   512
#define BATCH 2048
#define HID   512
#define KC    1024
#define NBLK  148
#define NTHR  512
#define NWRP  16
#define TILES 128           // 16 m-tiles x 8 h-tiles
#define STAGE 98304
#define OFF_AHI 0
#define OFF_ALO 16384
#define OFF_BHI 32768
#define OFF_BLO 65536
#define DYNSMEM (2*STAGE + 1024)
#define GSTR  264           // gates smem row stride (floats)
#define NRMAX 14

// ---------------- persistent device state (no allocs) ----------------
__device__ __align__(16) __nv_bfloat16 g_A_hi[BATCH * KC];   // [b][k] k<512:x0, k>=512:h
__device__ __align__(16) __nv_bfloat16 g_A_lo[BATCH * KC];
__device__ __align__(16) __nv_bfloat16 g_B_hi[8 * 256 * KC]; // [hb][n'][k], n'=gate*64+j
__device__ __align__(16) __nv_bfloat16 g_B_lo[8 * 256 * KC];
__device__ float g_bias[8 * 256];
__device__ float g_c[BATCH * HID];
__device__ float g_WiT[32 * HID];
__device__ float g_ypart[BATCH * 8];   // [b][hb] partial y dot products
__device__ unsigned g_bar_count;
__device__ volatile unsigned g_bar_gen;

// ---------------- helpers ----------------
__device__ __forceinline__ uint32_t smaddr(const void* p) {
    return (uint32_t)__cvta_generic_to_shared(p);
}
__device__ __forceinline__ void cpasync16(uint32_t dst, const void* src) {
    asm volatile("cp.async.cg.shared.global [%0], [%1], 16;" :: "r"(dst), "l"(src));
}
__device__ __forceinline__ void cp_commit() {
    asm volatile("cp.async.commit_group;" ::: "memory");
}
__device__ __forceinline__ void cp_wait1() {
    asm volatile("cp.async.wait_group 1;" ::: "memory");
}
__device__ __forceinline__ void cp_wait0() {
    asm volatile("cp.async.wait_group 0;" ::: "memory");
}
__device__ __forceinline__ void ldmx4(uint32_t* r, uint32_t addr) {
    asm volatile("ldmatrix.sync.aligned.m8n8.x4.shared.b16 {%0,%1,%2,%3}, [%4];"
                 : "=r"(r[0]), "=r"(r[1]), "=r"(r[2]), "=r"(r[3]) : "r"(addr));
}
__device__ __forceinline__ void mma16816(float* d, const uint32_t* a, const uint32_t* b) {
    asm volatile("mma.sync.aligned.m16n8k16.row.col.f32.bf16.bf16.f32 "
                 "{%0,%1,%2,%3}, {%4,%5,%6,%7}, {%8,%9}, {%0,%1,%2,%3};"
                 : "+f"(d[0]), "+f"(d[1]), "+f"(d[2]), "+f"(d[3])
                 : "r"(a[0]), "r"(a[1]), "r"(a[2]), "r"(a[3]), "r"(b[0]), "r"(b[1]));
}

__device__ __forceinline__ void grid_sync() {
    __syncthreads();
    if (threadIdx.x == 0) {
        unsigned gen = g_bar_gen;
        __threadfence();
        if (atomicAdd(&g_bar_count, 1u) == (unsigned)(NBLK - 1)) {
            g_bar_count = 0;
            __threadfence();
            g_bar_gen = gen + 1;
        } else {
            while (g_bar_gen == gen) { __nanosleep(64); }
        }
        __threadfence();
    }
    __syncthreads();
}

__device__ __forceinline__ float tanhap(float v) {
    float r;
    asm("tanh.approx.f32 %0, %1;" : "=f"(r) : "f"(v));
    return r;
}
__device__ __forceinline__ float sigap(float v) {
    return fmaf(0.5f, tanhap(0.5f * v), 0.5f);
}

// issue one k-slab (64 k) of A(hi/lo) + B(hi/lo) via cp.async into stage buffer
__device__ __forceinline__ void issue_slab(uint32_t dstbase, int kb, int m0, int hb, int tid) {
    #pragma unroll
    for (int i = 0; i < 2; ++i) {
        int c = tid + i * NTHR;
        int row = c >> 3, kq = c & 7;
        size_t so = ((size_t)(m0 + row) * KC + (size_t)kb * 64 + kq * 8) * 2;
        unsigned off = (unsigned)(row * 128) + (unsigned)((kq ^ (row & 7)) << 4);
        cpasync16(dstbase + OFF_AHI + off, (const char*)g_A_hi + so);
        cpasync16(dstbase + OFF_ALO + off, (const char*)g_A_lo + so);
    }
    #pragma unroll
    for (int i = 0; i < 4; ++i) {
        int c = tid + i * NTHR;
        int n = c >> 3, kq = c & 7;
        size_t so = (((size_t)hb * 256 + n) * KC + (size_t)kb * 64 + kq * 8) * 2;
        unsigned off = (unsigned)(n * 128) + (unsigned)((kq ^ (n & 7)) << 4);
        cpasync16(dstbase + OFF_BHI + off, (const char*)g_B_hi + so);
        cpasync16(dstbase + OFF_BLO + off, (const char*)g_B_lo + so);
    }
}

__global__ __launch_bounds__(NTHR, 1) void lstm_persist(
    const float* __restrict__ x,   const float* __restrict__ h0,
    const float* __restrict__ c0,  const float* __restrict__ y0,
    const float* __restrict__ W_in,  const float* __restrict__ b_in,
    const float* __restrict__ W_ih,  const float* __restrict__ W_hh,
    const float* __restrict__ b_ih,  const float* __restrict__ b_hh,
    const float* __restrict__ W_out, const float* __restrict__ b_out,
    float* __restrict__ out)
{
    extern __shared__ char dsm[];
    __shared__ float binS [HID];
    __shared__ float woutS[HID];
    __shared__ float biasS[256];
    __shared__ float inpS [NRMAX * 32];

    const int tid  = threadIdx.x;
    const int bid  = blockIdx.x;
    const int warp = tid >> 5, lane = tid & 31;

    // align dynamic smem to 1KB
    uint32_t raw = smaddr(dsm);
    uint32_t sb  = (raw + 1023u) & ~1023u;
    char* base   = dsm + (sb - raw);

    // ---- small per-CTA staging ----
    for (int i = tid; i < HID; i += NTHR) { binS[i] = b_in[i]; woutS[i] = W_out[i]; }

    // ---- one-time global init (striped across grid) ----
    for (int idx = bid * NTHR + tid; idx < 32 * HID; idx += NBLK * NTHR) {
        int j = idx >> 5, k = idx & 31;
        g_WiT[k * HID + j] = W_in[j * 32 + k];
    }
    for (int idx = bid * NTHR + tid; idx < 8 * 256 * KC; idx += NBLK * NTHR) {
        int hb = idx >> 18, rem = idx & 0x3FFFF;
        int n = rem >> 10, k = rem & 1023;
        int gate = n >> 6, j = n & 63;
        int srow = gate * 512 + hb * 64 + j;
        float w = (k < 512) ? W_ih[srow * 512 + k] : W_hh[srow * 512 + (k - 512)];
        __nv_bfloat16 hi = __float2bfloat16(w);
        g_B_hi[idx] = hi;
        g_B_lo[idx] = __float2bfloat16(w - __bfloat162float(hi));
    }
    for (int idx = bid * NTHR + tid; idx < 8 * 256; idx += NBLK * NTHR) {
        int hb = idx >> 8, n = idx & 255;
        int gate = n >> 6, j = n & 63;
        int srow = gate * 512 + hb * 64 + j;
        g_bias[idx] = b_ih[srow] + b_hh[srow];
    }
    grid_sync();

    const int m0 = (bid & 15) * 128;
    const int hb = bid >> 4;
    if (bid < TILES) {
        for (int i = tid; i < 256; i += NTHR) biasS[i] = g_bias[hb * 256 + i];
    }

    const int b0 = (bid * BATCH) / NBLK;
    const int b1 = ((bid + 1) * BATCH) / NBLK;
    const int NR = b1 - b0;
    const float bout0 = b_out[0];

    // ---- MMA thread-geometry (16 warps, 32x64 warp tile) ----
    const int warp_m = warp & 3;          // 0..3 -> 32-row block
    const int warp_n = warp >> 2;         // 0..3 -> gate (64-col block)
    const int l7 = lane & 7, q = lane >> 3;
    const int aRowL = warp_m * 32 + (q & 1) * 8 + l7;   // + mf*16
    const int cA    = q >> 1;
    const int bRowL = warp_n * 64 + (q >> 1) * 8 + l7;  // + bp*16
    const int cB    = q & 1;

    for (int t = 0; t <= SEQ; ++t) {
        // ================= ROW PHASE =================
        if (t == 0) {
            for (int b = b0 + warp; b < b1; b += NWRP) {
                for (int jj = lane; jj < HID; jj += 32) {
                    float h = h0[b * HID + jj];
                    __nv_bfloat16 hi = __float2bfloat16(h);
                    g_A_hi[(size_t)b * KC + 512 + jj] = hi;
                    g_A_lo[(size_t)b * KC + 512 + jj] =
                        __float2bfloat16(h - __bfloat162float(hi));
                    g_c[(size_t)b * HID + jj] = c0[b * HID + jj];
                }
            }
        }
        // ---- y per row (sum of 8 epilogue partials), write out ----
        if (tid < NR) {
            const int b = b0 + tid;
            float yv;
            if (t == 0) {
                yv = y0[b];
            } else {
                float s = bout0;
                #pragma unroll
                for (int p = 0; p < 8; ++p)
                    s += __ldcg(&g_ypart[(size_t)b * 8 + p]);
                out[(size_t)(t - 1) * BATCH + b] = s;
                yv = s;
            }
            if (t < SEQ) inpS[tid * 32 + 31] = yv;
        }
        if (t == SEQ) break;

        // ---- stage x into inpS ----
        for (int i = tid; i < NR * 31; i += NTHR) {
            int r = i / 31, cc = i - r * 31;
            inpS[r * 32 + cc] = __ldcg(&x[((size_t)t * BATCH + (b0 + r)) * 31 + cc]);
        }
        __syncthreads();

        // ---- x0 GEMM: 8 col-groups x 2 row-halves over 16 warps ----
        {
            const int half = warp >> 3;
            const int jc   = (warp & 7) * 64 + lane * 2;
            const int rmid = (NR + 1) >> 1;
            const int rlo  = half ? rmid : 0;
            const int rcnt = (half ? NR : rmid) - rlo;
            const float2 bb = *(const float2*)(binS + jc);
            float2 ac[7];
            #pragma unroll
            for (int r = 0; r < 7; ++r) ac[r] = bb;
            #pragma unroll 8
            for (int k = 0; k < 32; ++k) {
                const float2 w = *(const float2*)(g_WiT + k * HID + jc);
                #pragma unroll
                for (int r = 0; r < 7; ++r) {
                    if (r < rcnt) {
                        const float a = inpS[(rlo + r) * 32 + k];
                        ac[r].x = fmaf(a, w.x, ac[r].x);
                        ac[r].y = fmaf(a, w.y, ac[r].y);
                    }
                }
            }
            #pragma unroll
            for (int r = 0; r < 7; ++r) {
                if (r < rcnt) {
                    float vx = fmaxf(ac[r].x, 0.f), vy = fmaxf(ac[r].y, 0.f);
                    __nv_bfloat16 hx = __float2bfloat16(vx);
                    __nv_bfloat16 hy = __float2bfloat16(vy);
                    *(__nv_bfloat162*)(g_A_hi + (size_t)(b0 + rlo + r) * KC + jc) =
                        __halves2bfloat162(hx, hy);
                    *(__nv_bfloat162*)(g_A_lo + (size_t)(b0 + rlo + r) * KC + jc) =
                        __halves2bfloat162(
                            __float2bfloat16(vx - __bfloat162float(hx)),
                            __float2bfloat16(vy - __bfloat162float(hy)));
                }
            }
        }

        grid_sync();   // A complete -> GEMM may read

        // ================= MMA PHASE (mma.sync bf16, split hi/lo) =================
        if (bid < TILES) {
            float acc[2][8][4];
            #pragma unroll
            for (int mf = 0; mf < 2; ++mf)
                #pragma unroll
                for (int nf = 0; nf < 8; ++nf)
                    #pragma unroll
                    for (int e = 0; e < 4; ++e) acc[mf][nf][e] = 0.f;

            issue_slab(sb, 0, m0, hb, tid); cp_commit();
            issue_slab(sb + STAGE, 1, m0, hb, tid); cp_commit();

            for (int kb = 0; kb < 16; ++kb) {
                if (kb < 15) cp_wait1(); else cp_wait0();
                __syncthreads();
                const uint32_t bufb = sb + (uint32_t)(kb & 1) * STAGE;
                #pragma unroll
                for (int s4i = 0; s4i < 4; ++s4i) {
                    const int s4 = (s4i + warp_n) & 3;  // dephase warps on same SMSP
                    uint32_t bh[4][4], bl[4][4];
                    #pragma unroll
                    for (int bp = 0; bp < 4; ++bp) {
                        uint32_t baddr = bufb + OFF_BHI
                            + (uint32_t)((bRowL + bp * 16) * 128)
                            + (uint32_t)((((2 * s4 + cB) ^ l7)) << 4);
                        ldmx4(bh[bp], baddr);
                        ldmx4(bl[bp], baddr + (OFF_BLO - OFF_BHI));
                    }
                    #pragma unroll
                    for (int mf = 0; mf < 2; ++mf) {
                        uint32_t ah[4], al[4];
                        uint32_t aaddr = bufb + OFF_AHI
                            + (uint32_t)((aRowL + mf * 16) * 128)
                            + (uint32_t)((((2 * s4 + cA) ^ l7)) << 4);
                        ldmx4(ah, aaddr);
                        ldmx4(al, aaddr + (OFF_ALO - OFF_AHI));
                        #pragma unroll
                        for (int nf = 0; nf < 8; ++nf)
                            mma16816(acc[mf][nf], ah, &bh[nf >> 1][(nf & 1) * 2]);
                        #pragma unroll
                        for (int nf = 0; nf < 8; ++nf)
                            mma16816(acc[mf][nf], ah, &bl[nf >> 1][(nf & 1) * 2]);
                        #pragma unroll
                        for (int nf = 0; nf < 8; ++nf)
                            mma16816(acc[mf][nf], al, &bh[nf >> 1][(nf & 1) * 2]);
                    }
                }
                __syncthreads();
                if (kb + 2 < 16) { issue_slab(sb + (uint32_t)(kb & 1) * STAGE, kb + 2, m0, hb, tid); cp_commit(); }
            }

            // ---- store accums to gates smem tile (reuse stage region) ----
            float* G = (float*)base;
            #pragma unroll
            for (int mf = 0; mf < 2; ++mf) {
                const int r = warp_m * 32 + mf * 16 + (lane >> 2);
                #pragma unroll
                for (int nf = 0; nf < 8; ++nf) {
                    const int c = warp_n * 64 + nf * 8 + 2 * (lane & 3);
                    *(float2*)&G[r * GSTR + c]       = make_float2(acc[mf][nf][0], acc[mf][nf][1]);
                    *(float2*)&G[(r + 8) * GSTR + c] = make_float2(acc[mf][nf][2], acc[mf][nf][3]);
                }
            }
            __syncthreads();

            // ---- fused LSTM epilogue: thread = (row, 16-col chunk) ----
            const int r  = tid >> 2;            // 0..127
            const int jb = (tid & 3) * 16;      // 0..48
            const int rg = m0 + r;
            float* crow = g_c + (size_t)rg * HID + hb * 64;
            __nv_bfloat16* hrow_hi = g_A_hi + (size_t)rg * KC + 512 + hb * 64;
            __nv_bfloat16* hrow_lo = g_A_lo + (size_t)rg * KC + 512 + hb * 64;
            float ypart = 0.f;
            #pragma unroll
            for (int j = 0; j < 16; j += 4) {
                const int jj = jb + j;
                float4 vi = *(const float4*)&G[r * GSTR + 0   + jj];
                float4 vf = *(const float4*)&G[r * GSTR + 64  + jj];
                float4 vg = *(const float4*)&G[r * GSTR + 128 + jj];
                float4 vo = *(const float4*)&G[r * GSTR + 192 + jj];
                float4 cv = *(const float4*)(crow + jj);
                float I0 = sigap(vi.x + biasS[jj]);
                float I1 = sigap(vi.y + biasS[jj + 1]);
                float I2 = sigap(vi.z + biasS[jj + 2]);
                float I3 = sigap(vi.w + biasS[jj + 3]);
                float F0 = sigap(vf.x + biasS[64 + jj]);
                float F1 = sigap(vf.y + biasS[64 + jj + 1]);
                float F2 = sigap(vf.z + biasS[64 + jj + 2]);
                float F3 = sigap(vf.w + biasS[64 + jj + 3]);
                float G0 = tanhap(vg.x + biasS[128 + jj]);
                float G1 = tanhap(vg.y + biasS[128 + jj + 1]);
                float G2 = tanhap(vg.z + biasS[128 + jj + 2]);
                float G3 = tanhap(vg.w + biasS[128 + jj + 3]);
                float O0 = sigap(vo.x + biasS[192 + jj]);
                float O1 = sigap(vo.y + biasS[192 + jj + 1]);
                float O2 = sigap(vo.z + biasS[192 + jj + 2]);
                float O3 = sigap(vo.w + biasS[192 + jj + 3]);
                float4 cn;
                cn.x = F0 * cv.x + I0 * G0;
                cn.y = F1 * cv.y + I1 * G1;
                cn.z = F2 * cv.z + I2 * G2;
                cn.w = F3 * cv.w + I3 * G3;
                *(float4*)(crow + jj) = cn;
                float h0f = O0 * tanhap(cn.x);
                float h1f = O1 * tanhap(cn.y);
                float h2f = O2 * tanhap(cn.z);
                float h3f = O3 * tanhap(cn.w);
                const float4 wv = *(const float4*)(woutS + hb * 64 + jj);
                ypart += h0f * wv.x + h1f * wv.y + h2f * wv.z + h3f * wv.w;
                __nv_bfloat16 hh0 = __float2bfloat16(h0f);
                __nv_bfloat16 hh1 = __float2bfloat16(h1f);
                __nv_bfloat16 hh2 = __float2bfloat16(h2f);
                __nv_bfloat16 hh3 = __float2bfloat16(h3f);
                *(__nv_bfloat162*)(hrow_hi + jj)     = __halves2bfloat162(hh0, hh1);
                *(__nv_bfloat162*)(hrow_hi + jj + 2) = __halves2bfloat162(hh2, hh3);
                *(__nv_bfloat162*)(hrow_lo + jj) = __halves2bfloat162(
                    __float2bfloat16(h0f - __bfloat162float(hh0)),
                    __float2bfloat16(h1f - __bfloat162float(hh1)));
                *(__nv_bfloat162*)(hrow_lo + jj + 2) = __halves2bfloat162(
                    __float2bfloat16(h2f - __bfloat162float(hh2)),
                    __float2bfloat16(h3f - __bfloat162float(hh3)));
            }
            // reduce 4 chunk-partials of this row (lanes 4g..4g+3)
            ypart += __shfl_xor_sync(0xffffffffu, ypart, 1);
            ypart += __shfl_xor_sync(0xffffffffu, ypart, 2);
            if ((lane & 3) == 0) g_ypart[(size_t)rg * 8 + hb] = ypart;
        }

        grid_sync();   // h + ypart complete -> next row phase may read
    }
}

extern "C" void kernel_launch(void* const* d_in, const int* in_sizes, int n_in,
                              void* d_out, int out_size) {
    (void)in_sizes; (void)n_in; (void)out_size;
    const float* x     = (const float*)d_in[0];
    const float* h0    = (const float*)d_in[1];
    const float* c0    = (const float*)d_in[2];
    const float* y0    = (const float*)d_in[3];
    const float* W_in  = (const float*)d_in[4];
    const float* b_in  = (const float*)d_in[5];
    const float* W_ih  = (const float*)d_in[6];
    const float* W_hh  = (const float*)d_in[7];
    const float* b_ih  = (const float*)d_in[8];
    const float* b_hh  = (const float*)d_in[9];
    const float* W_out = (const float*)d_in[10];
    const float* b_out = (const float*)d_in[11];
    float* out = (float*)d_out;

    cudaFuncSetAttribute(lstm_persist, cudaFuncAttributeMaxDynamicSharedMemorySize, DYNSMEM);
    lstm_persist<<<NBLK, NTHR, DYNSMEM>>>(x, h0, c0, y0, W_in, b_in, W_ih, W_hh,
                                          b_ih, b_hh, W_out, b_out, out);
}

// round 9
// speedup vs baseline: 1.3265x; 1.3265x over previous
#include <cuda_runtime.h>
#include <cuda_fp16.h>
#include <math.h>
#include <stdint.h>

#define SEQ   512
#define BATCH 2048
#define HID   512
#define KC    1024
#define NBLK  148
#define NTHR  256
#define TILES 128           // 16 m-tiles x 8 h-tiles
#define STAGE 81920
#define OFF_A   0
#define OFF_BHI 16384
#define OFF_BLO 49152
#define DYNSMEM (2*STAGE + 1024)
#define NRMAX 14

// ---------------- persistent device state (no allocs) ----------------
__device__ __align__(16) __half g_A [BATCH * KC];     // [b][k] k<512:x0, k>=512:h (fp16)
__device__ __align__(16) __half g_B_hi[8 * 256 * KC]; // [hb][n'][k], n'=gate*64+j
__device__ __align__(16) __half g_B_lo[8 * 256 * KC]; // residual (subnormal range)
__device__ float g_bias[8 * 256];
__device__ float g_c[BATCH * HID];
__device__ float g_WiT[32 * HID];
__device__ float g_ypart[BATCH * 8];   // [b][hb] partial y dot products
__device__ unsigned g_cnt1[8 * 32];    // group counters (128B apart)
__device__ unsigned g_cnt2;
__device__ volatile unsigned g_bar_gen;

// ---------------- helpers ----------------
__device__ __forceinline__ uint32_t smaddr(const void* p) {
    return (uint32_t)__cvta_generic_to_shared(p);
}
__device__ __forceinline__ void cpasync16(uint32_t dst, const void* src) {
    asm volatile("cp.async.cg.shared.global [%0], [%1], 16;" :: "r"(dst), "l"(src));
}
__device__ __forceinline__ void cp_commit() {
    asm volatile("cp.async.commit_group;" ::: "memory");
}
__device__ __forceinline__ void cp_wait1() {
    asm volatile("cp.async.wait_group 1;" ::: "memory");
}
__device__ __forceinline__ void cp_wait0() {
    asm volatile("cp.async.wait_group 0;" ::: "memory");
}
__device__ __forceinline__ void ldmx4(uint32_t* r, uint32_t addr) {
    asm volatile("ldmatrix.sync.aligned.m8n8.x4.shared.b16 {%0,%1,%2,%3}, [%4];"
                 : "=r"(r[0]), "=r"(r[1]), "=r"(r[2]), "=r"(r[3]) : "r"(addr));
}
__device__ __forceinline__ void mma16816(float* d, const uint32_t* a, const uint32_t* b) {
    asm volatile("mma.sync.aligned.m16n8k16.row.col.f32.f16.f16.f32 "
                 "{%0,%1,%2,%3}, {%4,%5,%6,%7}, {%8,%9}, {%0,%1,%2,%3};"
                 : "+f"(d[0]), "+f"(d[1]), "+f"(d[2]), "+f"(d[3])
                 : "r"(a[0]), "r"(a[1]), "r"(a[2]), "r"(a[3]), "r"(b[0]), "r"(b[1]));
}

// two-level grid barrier: 8 groups (18/19 CTAs) -> 8-wide root
__device__ __forceinline__ void grid_sync() {
    __syncthreads();
    if (threadIdx.x == 0) {
        unsigned gen = g_bar_gen;
        __threadfence();
        const int grp = blockIdx.x & 7;
        const unsigned gsz = 18u + (grp < 4 ? 1u : 0u);
        if (atomicAdd(&g_cnt1[grp * 32], 1u) == gsz - 1u) {
            g_cnt1[grp * 32] = 0u;
            __threadfence();
            if (atomicAdd(&g_cnt2, 1u) == 7u) {
                g_cnt2 = 0u;
                __threadfence();
                g_bar_gen = gen + 1u;
            }
        }
        while (g_bar_gen == gen) { __nanosleep(64); }
        __threadfence();
    }
    __syncthreads();
}

__device__ __forceinline__ float tanhap(float v) {
    float r;
    asm("tanh.approx.f32 %0, %1;" : "=f"(r) : "f"(v));
    return r;
}
__device__ __forceinline__ float sigap(float v) {
    return fmaf(0.5f, tanhap(0.5f * v), 0.5f);
}

// issue one k-slab (64 k) of A + B(hi/lo) via cp.async into stage buffer
__device__ __forceinline__ void issue_slab(uint32_t dstbase, int kb, int m0, int hb, int tid) {
    #pragma unroll
    for (int i = 0; i < 4; ++i) {
        int c = tid + i * NTHR;
        int row = c >> 3, kq = c & 7;
        size_t so = ((size_t)(m0 + row) * KC + (size_t)kb * 64 + kq * 8) * 2;
        unsigned off = (unsigned)(row * 128) + (unsigned)((kq ^ (row & 7)) << 4);
        cpasync16(dstbase + OFF_A + off, (const char*)g_A + so);
    }
    #pragma unroll
    for (int i = 0; i < 8; ++i) {
        int c = tid + i * NTHR;
        int n = c >> 3, kq = c & 7;
        size_t so = (((size_t)hb * 256 + n) * KC + (size_t)kb * 64 + kq * 8) * 2;
        unsigned off = (unsigned)(n * 128) + (unsigned)((kq ^ (n & 7)) << 4);
        cpasync16(dstbase + OFF_BHI + off, (const char*)g_B_hi + so);
        cpasync16(dstbase + OFF_BLO + off, (const char*)g_B_lo + so);
    }
}

__global__ __launch_bounds__(NTHR, 1) void lstm_persist(
    const float* __restrict__ x,   const float* __restrict__ h0,
    const float* __restrict__ c0,  const float* __restrict__ y0,
    const float* __restrict__ W_in,  const float* __restrict__ b_in,
    const float* __restrict__ W_ih,  const float* __restrict__ W_hh,
    const float* __restrict__ b_ih,  const float* __restrict__ b_hh,
    const float* __restrict__ W_out, const float* __restrict__ b_out,
    float* __restrict__ out)
{
    extern __shared__ char dsm[];
    __shared__ float binS [HID];
    __shared__ float woutS[HID];
    __shared__ float biasS[256];
    __shared__ float inpS [NRMAX * 32];
    __shared__ float ypartS[128];

    const int tid  = threadIdx.x;
    const int bid  = blockIdx.x;
    const int warp = tid >> 5, lane = tid & 31;

    // align dynamic smem to 1KB
    uint32_t raw = smaddr(dsm);
    uint32_t sb  = (raw + 1023u) & ~1023u;

    // ---- small per-CTA staging ----
    for (int i = tid; i < HID; i += NTHR) { binS[i] = b_in[i]; woutS[i] = W_out[i]; }
    if (tid < 128) ypartS[tid] = 0.f;

    // ---- one-time global init (striped across grid) ----
    for (int idx = bid * NTHR + tid; idx < 32 * HID; idx += NBLK * NTHR) {
        int j = idx >> 5, k = idx & 31;
        g_WiT[k * HID + j] = W_in[j * 32 + k];
    }
    for (int idx = bid * NTHR + tid; idx < 8 * 256 * KC; idx += NBLK * NTHR) {
        int hb = idx >> 18, rem = idx & 0x3FFFF;
        int n = rem >> 10, k = rem & 1023;
        int gate = n >> 6, j = n & 63;
        int srow = gate * 512 + hb * 64 + j;
        float w = (k < 512) ? W_ih[srow * 512 + k] : W_hh[srow * 512 + (k - 512)];
        __half hi = __float2half_rn(w);
        g_B_hi[idx] = hi;
        g_B_lo[idx] = __float2half_rn(w - __half2float(hi));
    }
    for (int idx = bid * NTHR + tid; idx < 8 * 256; idx += NBLK * NTHR) {
        int hb = idx >> 8, n = idx & 255;
        int gate = n >> 6, j = n & 63;
        int srow = gate * 512 + hb * 64 + j;
        g_bias[idx] = b_ih[srow] + b_hh[srow];
    }
    grid_sync();

    const int m0 = (bid & 15) * 128;
    const int hb = bid >> 4;
    if (bid < TILES) {
        for (int i = tid; i < 256; i += NTHR) biasS[i] = g_bias[hb * 256 + i];
    }

    const int b0 = (bid * BATCH) / NBLK;
    const int b1 = ((bid + 1) * BATCH) / NBLK;
    const int NR = b1 - b0;
    const float bout0 = b_out[0];

    // ---- MMA thread-geometry (8 warps, 64x64 warp tile) ----
    // warp_n = 16-col slice index (same cols across all 4 gates -> register epilogue)
    const int warp_m = warp & 1;          // 0/1 -> rows 0-63 / 64-127
    const int warp_n = warp >> 1;         // 0..3 -> 16-col slice within each gate
    const int l7 = lane & 7, q = lane >> 3;
    const int aRowL = warp_m * 64 + (q & 1) * 8 + l7;        // + mf*16
    const int cA    = q >> 1;
    const int bRowL = warp_n * 16 + (q >> 1) * 8 + l7;       // + gate*64
    const int cB    = q & 1;
    const int lq  = lane >> 2;
    const int lc2 = 2 * (lane & 3);

    for (int t = 0; t <= SEQ; ++t) {
        // ================= ROW PHASE =================
        if (t == 0) {
            for (int b = b0 + warp; b < b1; b += 8) {
                for (int jj = lane; jj < HID; jj += 32) {
                    g_A[(size_t)b * KC + 512 + jj] = __float2half_rn(h0[b * HID + jj]);
                    g_c[(size_t)b * HID + jj] = c0[b * HID + jj];
                }
            }
        }
        // ---- y per row (sum of 8 epilogue partials), write out ----
        if (tid < NR) {
            const int b = b0 + tid;
            float yv;
            if (t == 0) {
                yv = y0[b];
            } else {
                float s = bout0;
                #pragma unroll
                for (int p = 0; p < 8; ++p)
                    s += __ldcg(&g_ypart[(size_t)b * 8 + p]);
                out[(size_t)(t - 1) * BATCH + b] = s;
                yv = s;
            }
            if (t < SEQ) inpS[tid * 32 + 31] = yv;
        }
        if (t == SEQ) break;

        // ---- stage x into inpS ----
        for (int i = tid; i < NR * 31; i += NTHR) {
            int r = i / 31, cc = i - r * 31;
            inpS[r * 32 + cc] = __ldcg(&x[((size_t)t * BATCH + (b0 + r)) * 31 + cc]);
        }
        __syncthreads();

        // ---- col-block x0 GEMM: warp owns 64 cols, lane owns 2, all NR rows ----
        {
            const int jc = warp * 64 + lane * 2;
            const float2 bb = *(const float2*)(binS + jc);
            float2 ac[NRMAX];
            #pragma unroll
            for (int r = 0; r < NRMAX; ++r) ac[r] = bb;
            #pragma unroll 4
            for (int k = 0; k < 32; ++k) {
                const float2 w = *(const float2*)(g_WiT + k * HID + jc);
                #pragma unroll
                for (int r = 0; r < NRMAX; ++r) {
                    if (r < NR) {
                        const float a = inpS[r * 32 + k];
                        ac[r].x = fmaf(a, w.x, ac[r].x);
                        ac[r].y = fmaf(a, w.y, ac[r].y);
                    }
                }
            }
            #pragma unroll
            for (int r = 0; r < NRMAX; ++r) {
                if (r < NR) {
                    float vx = fmaxf(ac[r].x, 0.f), vy = fmaxf(ac[r].y, 0.f);
                    *(__half2*)(g_A + (size_t)(b0 + r) * KC + jc) =
                        __floats2half2_rn(vx, vy);
                }
            }
        }

        grid_sync();   // A complete -> GEMM may read

        // ================= MMA PHASE (mma.sync fp16, 2-term W split) ============
        if (bid < TILES) {
            float acc[4][8][4];
            #pragma unroll
            for (int mf = 0; mf < 4; ++mf)
                #pragma unroll
                for (int nf = 0; nf < 8; ++nf)
                    #pragma unroll
                    for (int e = 0; e < 4; ++e) acc[mf][nf][e] = 0.f;

            issue_slab(sb, 0, m0, hb, tid); cp_commit();
            issue_slab(sb + STAGE, 1, m0, hb, tid); cp_commit();

            for (int kb = 0; kb < 16; ++kb) {
                if (kb < 15) cp_wait1(); else cp_wait0();
                __syncthreads();
                const uint32_t bufb = sb + (uint32_t)(kb & 1) * STAGE;
                #pragma unroll
                for (int s4i = 0; s4i < 4; ++s4i) {
                    const int s4 = (s4i + warp_n) & 3;   // dephase SMSP partners
                    uint32_t bh[4][4], bl[4][4];
                    #pragma unroll
                    for (int g = 0; g < 4; ++g) {        // gate-major B frags
                        uint32_t baddr = bufb + OFF_BHI
                            + (uint32_t)((bRowL + g * 64) * 128)
                            + (uint32_t)((((2 * s4 + cB) ^ l7)) << 4);
                        ldmx4(bh[g], baddr);
                        ldmx4(bl[g], baddr + (OFF_BLO - OFF_BHI));
                    }
                    #pragma unroll
                    for (int mf = 0; mf < 4; ++mf) {
                        uint32_t ah[4];
                        uint32_t aaddr = bufb + OFF_A
                            + (uint32_t)((aRowL + mf * 16) * 128)
                            + (uint32_t)((((2 * s4 + cA) ^ l7)) << 4);
                        ldmx4(ah, aaddr);
                        #pragma unroll
                        for (int nf = 0; nf < 8; ++nf)
                            mma16816(acc[mf][nf], ah, &bh[nf >> 1][(nf & 1) * 2]);
                        #pragma unroll
                        for (int nf = 0; nf < 8; ++nf)
                            mma16816(acc[mf][nf], ah, &bl[nf >> 1][(nf & 1) * 2]);
                    }
                }
                __syncthreads();
                if (kb + 2 < 16) { issue_slab(sb + (uint32_t)(kb & 1) * STAGE, kb + 2, m0, hb, tid); cp_commit(); }
            }

            // ---- register-resident LSTM epilogue (i,f,g,o all local) ----
            #pragma unroll
            for (int mf = 0; mf < 4; ++mf) {
                #pragma unroll
                for (int e2 = 0; e2 < 2; ++e2) {
                    const int r  = warp_m * 64 + mf * 16 + e2 * 8 + lq;
                    const int rg = m0 + r;
                    const int e0 = e2 * 2;
                    float yp = 0.f;
                    #pragma unroll
                    for (int sub = 0; sub < 2; ++sub) {
                        const int jl = warp_n * 16 + sub * 8 + lc2;   // 0..63
                        float I0 = sigap(acc[mf][0 + sub][e0]     + biasS[jl]);
                        float I1 = sigap(acc[mf][0 + sub][e0 + 1] + biasS[jl + 1]);
                        float F0 = sigap(acc[mf][2 + sub][e0]     + biasS[64 + jl]);
                        float F1 = sigap(acc[mf][2 + sub][e0 + 1] + biasS[64 + jl + 1]);
                        float G0 = tanhap(acc[mf][4 + sub][e0]     + biasS[128 + jl]);
                        float G1 = tanhap(acc[mf][4 + sub][e0 + 1] + biasS[128 + jl + 1]);
                        float O0 = sigap(acc[mf][6 + sub][e0]     + biasS[192 + jl]);
                        float O1 = sigap(acc[mf][6 + sub][e0 + 1] + biasS[192 + jl + 1]);
                        float* cp = g_c + (size_t)rg * HID + hb * 64 + jl;
                        float2 cv = *(float2*)cp;
                        float cn0 = F0 * cv.x + I0 * G0;
                        float cn1 = F1 * cv.y + I1 * G1;
                        *(float2*)cp = make_float2(cn0, cn1);
                        float h0f = O0 * tanhap(cn0);
                        float h1f = O1 * tanhap(cn1);
                        const float2 wv = *(const float2*)(woutS + hb * 64 + jl);
                        yp = fmaf(h0f, wv.x, fmaf(h1f, wv.y, yp));
                        *(__half2*)(g_A + (size_t)rg * KC + 512 + hb * 64 + jl) =
                            __floats2half2_rn(h0f, h1f);
                    }
                    yp += __shfl_xor_sync(0xffffffffu, yp, 1);
                    yp += __shfl_xor_sync(0xffffffffu, yp, 2);
                    if ((lane & 3) == 0) atomicAdd(&ypartS[r], yp);
                }
            }
            __syncthreads();
            if (tid < 128) {
                g_ypart[(size_t)(m0 + tid) * 8 + hb] = ypartS[tid];
                ypartS[tid] = 0.f;
            }
        }

        grid_sync();   // h + ypart complete -> next row phase may read
    }
}

extern "C" void kernel_launch(void* const* d_in, const int* in_sizes, int n_in,
                              void* d_out, int out_size) {
    (void)in_sizes; (void)n_in; (void)out_size;
    const float* x     = (const float*)d_in[0];
    const float* h0    = (const float*)d_in[1];
    const float* c0    = (const float*)d_in[2];
    const float* y0    = (const float*)d_in[3];
    const float* W_in  = (const float*)d_in[4];
    const float* b_in  = (const float*)d_in[5];
    const float* W_ih  = (const float*)d_in[6];
    const float* W_hh  = (const float*)d_in[7];
    const float* b_ih  = (const float*)d_in[8];
    const float* b_hh  = (const float*)d_in[9];
    const float* W_out = (const float*)d_in[10];
    const float* b_out = (const float*)d_in[11];
    float* out = (float*)d_out;

    cudaFuncSetAttribute(lstm_persist, cudaFuncAttributeMaxDynamicSharedMemorySize, DYNSMEM);
    lstm_persist<<<NBLK, NTHR, DYNSMEM>>>(x, h0, c0, y0, W_in, b_in, W_ih, W_hh,
                                          b_ih, b_hh, W_out, b_out, out);
}

// round 10
// speedup vs baseline: 2.0018x; 1.5090x over previous
#include <cuda_runtime.h>
#include <cuda_fp16.h>
#include <math.h>
#include <stdint.h>

#define SEQ   512
#define BATCH 2048
#define HID   512
#define KC    1024
#define AKC   1536          // g_A row stride: [x0(512) | h_even(512) | h_odd(512)]
#define NBLK  148
#define NTHR  256
#define TILES 128           // 16 m-tiles x 8 h-tiles
#define STAGE 49152
#define OFF_A 0
#define OFF_B 16384
#define DYNSMEM (2*STAGE + 1024)
#define NRMAX 14

// ---------------- persistent device state (no allocs) ----------------
__device__ __align__(16) __half g_A [BATCH * AKC];    // fp16 activations
__device__ __align__(16) __half g_B [8 * 256 * KC];   // [hb][n'][k] fp16 weights
__device__ float g_bias[8 * 256];
__device__ float g_c[BATCH * HID];
__device__ float g_WiT[32 * HID];
__device__ float g_ypart[BATCH * 8];   // [b][hb] partial y dot products
__device__ unsigned g_cnt1[8 * 32];    // group counters (128B apart)
__device__ unsigned g_cnt2;
__device__ volatile unsigned g_bar_gen;

// ---------------- helpers ----------------
__device__ __forceinline__ uint32_t smaddr(const void* p) {
    return (uint32_t)__cvta_generic_to_shared(p);
}
__device__ __forceinline__ void cpasync16(uint32_t dst, const void* src) {
    asm volatile("cp.async.cg.shared.global [%0], [%1], 16;" :: "r"(dst), "l"(src));
}
__device__ __forceinline__ void cp_commit() {
    asm volatile("cp.async.commit_group;" ::: "memory");
}
__device__ __forceinline__ void cp_wait1() {
    asm volatile("cp.async.wait_group 1;" ::: "memory");
}
__device__ __forceinline__ void cp_wait0() {
    asm volatile("cp.async.wait_group 0;" ::: "memory");
}
__device__ __forceinline__ void ldmx4(uint32_t* r, uint32_t addr) {
    asm volatile("ldmatrix.sync.aligned.m8n8.x4.shared.b16 {%0,%1,%2,%3}, [%4];"
                 : "=r"(r[0]), "=r"(r[1]), "=r"(r[2]), "=r"(r[3]) : "r"(addr));
}
__device__ __forceinline__ void mma16816(float* d, const uint32_t* a, const uint32_t* b) {
    asm volatile("mma.sync.aligned.m16n8k16.row.col.f32.f16.f16.f32 "
                 "{%0,%1,%2,%3}, {%4,%5,%6,%7}, {%8,%9}, {%0,%1,%2,%3};"
                 : "+f"(d[0]), "+f"(d[1]), "+f"(d[2]), "+f"(d[3])
                 : "r"(a[0]), "r"(a[1]), "r"(a[2]), "r"(a[3]), "r"(b[0]), "r"(b[1]));
}

// two-level grid barrier: 8 groups (18/19 CTAs) -> 8-wide root
__device__ __forceinline__ void grid_sync() {
    __syncthreads();
    if (threadIdx.x == 0) {
        unsigned gen = g_bar_gen;
        __threadfence();
        const int grp = blockIdx.x & 7;
        const unsigned gsz = 18u + (grp < 4 ? 1u : 0u);
        if (atomicAdd(&g_cnt1[grp * 32], 1u) == gsz - 1u) {
            g_cnt1[grp * 32] = 0u;
            __threadfence();
            if (atomicAdd(&g_cnt2, 1u) == 7u) {
                g_cnt2 = 0u;
                __threadfence();
                g_bar_gen = gen + 1u;
            }
        }
        while (g_bar_gen == gen) { __nanosleep(64); }
        __threadfence();
    }
    __syncthreads();
}

__device__ __forceinline__ float tanhap(float v) {
    float r;
    asm("tanh.approx.f32 %0, %1;" : "=f"(r) : "f"(v));
    return r;
}
__device__ __forceinline__ float sigap(float v) {
    return fmaf(0.5f, tanhap(0.5f * v), 0.5f);
}

// issue one k-slab (64 k) of A + B via cp.async into stage buffer.
// kb 0..7 = x0 half (k 0..511); kb 8..15 = h half, phase p selects h buffer.
__device__ __forceinline__ void issue_slab(uint32_t dstbase, int kb, int m0, int hb,
                                           int tid, int p) {
    const int ksrcA = kb * 64 + ((kb >= 8) ? p * 512 : 0);
    #pragma unroll
    for (int i = 0; i < 4; ++i) {
        int c = tid + i * NTHR;
        int row = c >> 3, kq = c & 7;
        size_t so = ((size_t)(m0 + row) * AKC + ksrcA + kq * 8) * 2;
        unsigned off = (unsigned)(row * 128) + (unsigned)((kq ^ (row & 7)) << 4);
        cpasync16(dstbase + OFF_A + off, (const char*)g_A + so);
    }
    #pragma unroll
    for (int i = 0; i < 8; ++i) {
        int c = tid + i * NTHR;
        int n = c >> 3, kq = c & 7;
        size_t so = (((size_t)hb * 256 + n) * KC + (size_t)kb * 64 + kq * 8) * 2;
        unsigned off = (unsigned)(n * 128) + (unsigned)((kq ^ (n & 7)) << 4);
        cpasync16(dstbase + OFF_B + off, (const char*)g_B + so);
    }
}

__global__ __launch_bounds__(NTHR, 1) void lstm_persist(
    const float* __restrict__ x,   const float* __restrict__ h0,
    const float* __restrict__ c0,  const float* __restrict__ y0,
    const float* __restrict__ W_in,  const float* __restrict__ b_in,
    const float* __restrict__ W_ih,  const float* __restrict__ W_hh,
    const float* __restrict__ b_ih,  const float* __restrict__ b_hh,
    const float* __restrict__ W_out, const float* __restrict__ b_out,
    float* __restrict__ out)
{
    extern __shared__ char dsm[];
    __shared__ float binS [HID];
    __shared__ float woutS[HID];
    __shared__ float biasS[256];
    __shared__ float inpS [NRMAX * 32];
    __shared__ float ypartS[128];

    const int tid  = threadIdx.x;
    const int bid  = blockIdx.x;
    const int warp = tid >> 5, lane = tid & 31;

    // align dynamic smem to 1KB
    uint32_t raw = smaddr(dsm);
    uint32_t sb  = (raw + 1023u) & ~1023u;

    // ---- small per-CTA staging ----
    for (int i = tid; i < HID; i += NTHR) { binS[i] = b_in[i]; woutS[i] = W_out[i]; }
    if (tid < 128) ypartS[tid] = 0.f;

    // ---- one-time global init (striped across grid) ----
    for (int idx = bid * NTHR + tid; idx < 32 * HID; idx += NBLK * NTHR) {
        int j = idx >> 5, k = idx & 31;
        g_WiT[k * HID + j] = W_in[j * 32 + k];
    }
    for (int idx = bid * NTHR + tid; idx < 8 * 256 * KC; idx += NBLK * NTHR) {
        int hb = idx >> 18, rem = idx & 0x3FFFF;
        int n = rem >> 10, k = rem & 1023;
        int gate = n >> 6, j = n & 63;
        int srow = gate * 512 + hb * 64 + j;
        float w = (k < 512) ? W_ih[srow * 512 + k] : W_hh[srow * 512 + (k - 512)];
        g_B[idx] = __float2half_rn(w);
    }
    for (int idx = bid * NTHR + tid; idx < 8 * 256; idx += NBLK * NTHR) {
        int hb = idx >> 8, n = idx & 255;
        int gate = n >> 6, j = n & 63;
        int srow = gate * 512 + hb * 64 + j;
        g_bias[idx] = b_ih[srow] + b_hh[srow];
    }
    grid_sync();

    const int m0 = (bid & 15) * 128;
    const int hb = bid >> 4;
    if (bid < TILES) {
        for (int i = tid; i < 256; i += NTHR) biasS[i] = g_bias[hb * 256 + i];
    }

    const int b0 = (bid * BATCH) / NBLK;
    const int b1 = ((bid + 1) * BATCH) / NBLK;
    const int NR = b1 - b0;
    const float bout0 = b_out[0];

    // ---- MMA thread-geometry (8 warps, 64x64 warp tile) ----
    const int warp_m = warp & 1;          // 0/1 -> rows 0-63 / 64-127
    const int warp_n = warp >> 1;         // 0..3 -> 16-col slice within each gate
    const int l7 = lane & 7, q = lane >> 3;
    const int aRowL = warp_m * 64 + (q & 1) * 8 + l7;        // + mf*16
    const int cA    = q >> 1;
    const int bRowL = warp_n * 16 + (q >> 1) * 8 + l7;       // + gate*64
    const int cB    = q & 1;
    const int lq  = lane >> 2;
    const int lc2 = 2 * (lane & 3);

    for (int t = 0; t <= SEQ; ++t) {
        const int p = t & 1;
        // ================= ROW PHASE =================
        if (t == 0) {
            for (int b = b0 + warp; b < b1; b += 8) {
                for (int jj = lane; jj < HID; jj += 32) {
                    g_A[(size_t)b * AKC + 512 + jj] = __float2half_rn(h0[b * HID + jj]);
                    g_c[(size_t)b * HID + jj] = c0[b * HID + jj];
                }
            }
        } else if (t < SEQ && bid < TILES) {
            // prefetch first two h-half slabs during row phase (h(t) ready since sync2)
            issue_slab(sb, 8, m0, hb, tid, p); cp_commit();
            issue_slab(sb + STAGE, 9, m0, hb, tid, p); cp_commit();
        }
        // ---- y per row (sum of 8 epilogue partials), write out ----
        if (tid < NR) {
            const int b = b0 + tid;
            float yv;
            if (t == 0) {
                yv = y0[b];
            } else {
                float s = bout0;
                #pragma unroll
                for (int pp = 0; pp < 8; ++pp)
                    s += __ldcg(&g_ypart[(size_t)b * 8 + pp]);
                out[(size_t)(t - 1) * BATCH + b] = s;
                yv = s;
            }
            if (t < SEQ) inpS[tid * 32 + 31] = yv;
        }
        if (t == SEQ) break;

        // ---- stage x into inpS ----
        for (int i = tid; i < NR * 31; i += NTHR) {
            int r = i / 31, cc = i - r * 31;
            inpS[r * 32 + cc] = __ldcg(&x[((size_t)t * BATCH + (b0 + r)) * 31 + cc]);
        }
        __syncthreads();

        // ---- col-block x0 GEMM: warp owns 64 cols, lane owns 2, all NR rows ----
        {
            const int jc = warp * 64 + lane * 2;
            const float2 bb = *(const float2*)(binS + jc);
            float2 ac[NRMAX];
            #pragma unroll
            for (int r = 0; r < NRMAX; ++r) ac[r] = bb;
            #pragma unroll 4
            for (int k = 0; k < 32; ++k) {
                const float2 w = *(const float2*)(g_WiT + k * HID + jc);
                #pragma unroll
                for (int r = 0; r < NRMAX; ++r) {
                    if (r < NR) {
                        const float a = inpS[r * 32 + k];
                        ac[r].x = fmaf(a, w.x, ac[r].x);
                        ac[r].y = fmaf(a, w.y, ac[r].y);
                    }
                }
            }
            #pragma unroll
            for (int r = 0; r < NRMAX; ++r) {
                if (r < NR) {
                    float vx = fmaxf(ac[r].x, 0.f), vy = fmaxf(ac[r].y, 0.f);
                    *(__half2*)(g_A + (size_t)(b0 + r) * AKC + jc) =
                        __floats2half2_rn(vx, vy);
                }
            }
        }

        grid_sync();   // A complete -> GEMM may read

        // ================= MMA PHASE (single-pass fp16 mma.sync) ============
        if (bid < TILES) {
            float acc[4][8][4];
            #pragma unroll
            for (int mf = 0; mf < 4; ++mf)
                #pragma unroll
                for (int nf = 0; nf < 8; ++nf)
                    #pragma unroll
                    for (int e = 0; e < 4; ++e) acc[mf][nf][e] = 0.f;

            if (t == 0) {   // no prefetch happened during row phase at t==0
                issue_slab(sb, 8, m0, hb, tid, p); cp_commit();
                issue_slab(sb + STAGE, 9, m0, hb, tid, p); cp_commit();
            }

            // slab order: h-half (kb 8..15) first, then x0-half (kb 0..7)
            for (int i = 0; i < 16; ++i) {
                if (i < 14) cp_wait1(); else cp_wait0();
                __syncthreads();
                const uint32_t bufb = sb + (uint32_t)(i & 1) * STAGE;
                #pragma unroll
                for (int s4i = 0; s4i < 4; ++s4i) {
                    const int s4 = (s4i + warp_n) & 3;   // dephase SMSP partners
                    uint32_t bh[4][4];
                    #pragma unroll
                    for (int g = 0; g < 4; ++g) {        // gate-major B frags
                        uint32_t baddr = bufb + OFF_B
                            + (uint32_t)((bRowL + g * 64) * 128)
                            + (uint32_t)((((2 * s4 + cB) ^ l7)) << 4);
                        ldmx4(bh[g], baddr);
                    }
                    #pragma unroll
                    for (int mf = 0; mf < 4; ++mf) {
                        uint32_t ah[4];
                        uint32_t aaddr = bufb + OFF_A
                            + (uint32_t)((aRowL + mf * 16) * 128)
                            + (uint32_t)((((2 * s4 + cA) ^ l7)) << 4);
                        ldmx4(ah, aaddr);
                        #pragma unroll
                        for (int nf = 0; nf < 8; ++nf)
                            mma16816(acc[mf][nf], ah, &bh[nf >> 1][(nf & 1) * 2]);
                    }
                }
                __syncthreads();
                if (i + 2 < 16) {
                    const int nkb = (i + 2 < 8) ? (8 + i + 2) : (i + 2 - 8);
                    issue_slab(sb + (uint32_t)(i & 1) * STAGE, nkb, m0, hb, tid, p);
                    cp_commit();
                }
            }

            // ---- register-resident LSTM epilogue (i,f,g,o all local) ----
            #pragma unroll
            for (int mf = 0; mf < 4; ++mf) {
                #pragma unroll
                for (int e2 = 0; e2 < 2; ++e2) {
                    const int r  = warp_m * 64 + mf * 16 + e2 * 8 + lq;
                    const int rg = m0 + r;
                    const int e0 = e2 * 2;
                    float yp = 0.f;
                    #pragma unroll
                    for (int sub = 0; sub < 2; ++sub) {
                        const int jl = warp_n * 16 + sub * 8 + lc2;   // 0..63
                        float I0 = sigap(acc[mf][0 + sub][e0]     + biasS[jl]);
                        float I1 = sigap(acc[mf][0 + sub][e0 + 1] + biasS[jl + 1]);
                        float F0 = sigap(acc[mf][2 + sub][e0]     + biasS[64 + jl]);
                        float F1 = sigap(acc[mf][2 + sub][e0 + 1] + biasS[64 + jl + 1]);
                        float G0 = tanhap(acc[mf][4 + sub][e0]     + biasS[128 + jl]);
                        float G1 = tanhap(acc[mf][4 + sub][e0 + 1] + biasS[128 + jl + 1]);
                        float O0 = sigap(acc[mf][6 + sub][e0]     + biasS[192 + jl]);
                        float O1 = sigap(acc[mf][6 + sub][e0 + 1] + biasS[192 + jl + 1]);
                        float* cp = g_c + (size_t)rg * HID + hb * 64 + jl;
                        float2 cv = *(float2*)cp;
                        float cn0 = F0 * cv.x + I0 * G0;
                        float cn1 = F1 * cv.y + I1 * G1;
                        *(float2*)cp = make_float2(cn0, cn1);
                        float h0f = O0 * tanhap(cn0);
                        float h1f = O1 * tanhap(cn1);
                        const float2 wv = *(const float2*)(woutS + hb * 64 + jl);
                        yp = fmaf(h0f, wv.x, fmaf(h1f, wv.y, yp));
                        // write h(t+1) into the OTHER h buffer (race-free)
                        *(__half2*)(g_A + (size_t)rg * AKC + 512 + (p ^ 1) * 512
                                    + hb * 64 + jl) = __floats2half2_rn(h0f, h1f);
                    }
                    yp += __shfl_xor_sync(0xffffffffu, yp, 1);
                    yp += __shfl_xor_sync(0xffffffffu, yp, 2);
                    if ((lane & 3) == 0) atomicAdd(&ypartS[r], yp);
                }
            }
            __syncthreads();
            if (tid < 128) {
                g_ypart[(size_t)(m0 + tid) * 8 + hb] = ypartS[tid];
                ypartS[tid] = 0.f;
            }
        }

        grid_sync();   // h + ypart complete -> next row phase may read
    }
}

extern "C" void kernel_launch(void* const* d_in, const int* in_sizes, int n_in,
                              void* d_out, int out_size) {
    (void)in_sizes; (void)n_in; (void)out_size;
    const float* x     = (const float*)d_in[0];
    const float* h0    = (const float*)d_in[1];
    const float* c0    = (const float*)d_in[2];
    const float* y0    = (const float*)d_in[3];
    const float* W_in  = (const float*)d_in[4];
    const float* b_in  = (const float*)d_in[5];
    const float* W_ih  = (const float*)d_in[6];
    const float* W_hh  = (const float*)d_in[7];
    const float* b_ih  = (const float*)d_in[8];
    const float* b_hh  = (const float*)d_in[9];
    const float* W_out = (const float*)d_in[10];
    const float* b_out = (const float*)d_in[11];
    float* out = (float*)d_out;

    cudaFuncSetAttribute(lstm_persist, cudaFuncAttributeMaxDynamicSharedMemorySize, DYNSMEM);
    lstm_persist<<<NBLK, NTHR, DYNSMEM>>>(x, h0, c0, y0, W_in, b_in, W_ih, W_hh,
                                          b_ih, b_hh, W_out, b_out, out);
}

// round 11
// speedup vs baseline: 2.0561x; 1.0271x over previous
#include <cuda_runtime.h>
#include <cuda_fp16.h>
#include <math.h>
#include <stdint.h>

#define SEQ   512
#define BATCH 2048
#define HID   512
#define KC    1024
#define AKC   1536          // g_A row stride: [x0(512) | h_even(512) | h_odd(512)]
#define NBLK  148
#define NTHR  256
#define TILES 128           // 16 m-tiles x 8 h-tiles
#define STAGE 49152
#define OFF_A 0
#define OFF_B 16384
#define DYNSMEM (4*STAGE + 1024)
#define NRMAX 14

// ---------------- persistent device state (no allocs) ----------------
__device__ __align__(16) __half g_A [BATCH * AKC];    // fp16 activations
__device__ __align__(16) __half g_B [8 * 256 * KC];   // [hb][n'][k] fp16 weights
__device__ float g_bias[8 * 256];
__device__ float g_c[BATCH * HID];
__device__ float g_WiT[32 * HID];
__device__ float g_ypart[BATCH * 8];   // [b][hb] partial y dot products
__device__ unsigned g_cnt1[8 * 32];    // group counters (128B apart)
__device__ unsigned g_cnt2;
__device__ volatile unsigned g_bar_gen;

// ---------------- helpers ----------------
__device__ __forceinline__ uint32_t smaddr(const void* p) {
    return (uint32_t)__cvta_generic_to_shared(p);
}
__device__ __forceinline__ void cpasync16(uint32_t dst, const void* src) {
    asm volatile("cp.async.cg.shared.global [%0], [%1], 16;" :: "r"(dst), "l"(src));
}
__device__ __forceinline__ void cpasync4(uint32_t dst, const void* src) {
    asm volatile("cp.async.ca.shared.global [%0], [%1], 4;" :: "r"(dst), "l"(src));
}
__device__ __forceinline__ void cp_commit() {
    asm volatile("cp.async.commit_group;" ::: "memory");
}
__device__ __forceinline__ void cp_wait2() {
    asm volatile("cp.async.wait_group 2;" ::: "memory");
}
__device__ __forceinline__ void cp_wait1() {
    asm volatile("cp.async.wait_group 1;" ::: "memory");
}
__device__ __forceinline__ void cp_wait0() {
    asm volatile("cp.async.wait_group 0;" ::: "memory");
}
__device__ __forceinline__ void ldmx4(uint32_t* r, uint32_t addr) {
    asm volatile("ldmatrix.sync.aligned.m8n8.x4.shared.b16 {%0,%1,%2,%3}, [%4];"
                 : "=r"(r[0]), "=r"(r[1]), "=r"(r[2]), "=r"(r[3]) : "r"(addr));
}
__device__ __forceinline__ void mma16816(float* d, const uint32_t* a, const uint32_t* b) {
    asm volatile("mma.sync.aligned.m16n8k16.row.col.f32.f16.f16.f32 "
                 "{%0,%1,%2,%3}, {%4,%5,%6,%7}, {%8,%9}, {%0,%1,%2,%3};"
                 : "+f"(d[0]), "+f"(d[1]), "+f"(d[2]), "+f"(d[3])
                 : "r"(a[0]), "r"(a[1]), "r"(a[2]), "r"(a[3]), "r"(b[0]), "r"(b[1]));
}

// two-level grid barrier: 8 groups (18/19 CTAs) -> 8-wide root; pure spin
__device__ __forceinline__ void grid_sync() {
    __syncthreads();
    if (threadIdx.x == 0) {
        unsigned gen = g_bar_gen;
        __threadfence();
        const int grp = blockIdx.x & 7;
        const unsigned gsz = 18u + (grp < 4 ? 1u : 0u);
        if (atomicAdd(&g_cnt1[grp * 32], 1u) == gsz - 1u) {
            g_cnt1[grp * 32] = 0u;
            __threadfence();
            if (atomicAdd(&g_cnt2, 1u) == 7u) {
                g_cnt2 = 0u;
                __threadfence();
                g_bar_gen = gen + 1u;
            }
        }
        while (g_bar_gen == gen) { }
        __threadfence();
    }
    __syncthreads();
}

__device__ __forceinline__ float tanhap(float v) {
    float r;
    asm("tanh.approx.f32 %0, %1;" : "=f"(r) : "f"(v));
    return r;
}
__device__ __forceinline__ float sigap(float v) {
    return fmaf(0.5f, tanhap(0.5f * v), 0.5f);
}

// process order i=0..15 -> kb: h-half (8..15) first, then x0-half (0..7)
__device__ __forceinline__ int kb_of(int i) { return (i < 8) ? (8 + i) : (i - 8); }

// issue one k-slab (64 k) of A + B via cp.async into stage buffer.
// kb 0..7 = x0 half (k 0..511); kb 8..15 = h half, phase p selects h buffer.
__device__ __forceinline__ void issue_slab(uint32_t dstbase, int kb, int m0, int hb,
                                           int tid, int p) {
    const int ksrcA = kb * 64 + ((kb >= 8) ? p * 512 : 0);
    #pragma unroll
    for (int i = 0; i < 4; ++i) {
        int c = tid + i * NTHR;
        int row = c >> 3, kq = c & 7;
        size_t so = ((size_t)(m0 + row) * AKC + ksrcA + kq * 8) * 2;
        unsigned off = (unsigned)(row * 128) + (unsigned)((kq ^ (row & 7)) << 4);
        cpasync16(dstbase + OFF_A + off, (const char*)g_A + so);
    }
    #pragma unroll
    for (int i = 0; i < 8; ++i) {
        int c = tid + i * NTHR;
        int n = c >> 3, kq = c & 7;
        size_t so = (((size_t)hb * 256 + n) * KC + (size_t)kb * 64 + kq * 8) * 2;
        unsigned off = (unsigned)(n * 128) + (unsigned)((kq ^ (n & 7)) << 4);
        cpasync16(dstbase + OFF_B + off, (const char*)g_B + so);
    }
}

__global__ __launch_bounds__(NTHR, 1) void lstm_persist(
    const float* __restrict__ x,   const float* __restrict__ h0,
    const float* __restrict__ c0,  const float* __restrict__ y0,
    const float* __restrict__ W_in,  const float* __restrict__ b_in,
    const float* __restrict__ W_ih,  const float* __restrict__ W_hh,
    const float* __restrict__ b_ih,  const float* __restrict__ b_hh,
    const float* __restrict__ W_out, const float* __restrict__ b_out,
    float* __restrict__ out)
{
    extern __shared__ char dsm[];
    __shared__ float binS [HID];
    __shared__ float woutS[HID];
    __shared__ float biasS[256];
    __shared__ float inpS [NRMAX * 32];
    __shared__ float ypartS[128];

    const int tid  = threadIdx.x;
    const int bid  = blockIdx.x;
    const int warp = tid >> 5, lane = tid & 31;

    // align dynamic smem to 1KB
    uint32_t raw = smaddr(dsm);
    uint32_t sb  = (raw + 1023u) & ~1023u;

    // ---- small per-CTA staging ----
    for (int i = tid; i < HID; i += NTHR) { binS[i] = b_in[i]; woutS[i] = W_out[i]; }
    if (tid < 128) ypartS[tid] = 0.f;

    // ---- one-time global init (striped across grid) ----
    for (int idx = bid * NTHR + tid; idx < 32 * HID; idx += NBLK * NTHR) {
        int j = idx >> 5, k = idx & 31;
        g_WiT[k * HID + j] = W_in[j * 32 + k];
    }
    for (int idx = bid * NTHR + tid; idx < 8 * 256 * KC; idx += NBLK * NTHR) {
        int hb = idx >> 18, rem = idx & 0x3FFFF;
        int n = rem >> 10, k = rem & 1023;
        int gate = n >> 6, j = n & 63;
        int srow = gate * 512 + hb * 64 + j;
        float w = (k < 512) ? W_ih[srow * 512 + k] : W_hh[srow * 512 + (k - 512)];
        g_B[idx] = __float2half_rn(w);
    }
    for (int idx = bid * NTHR + tid; idx < 8 * 256; idx += NBLK * NTHR) {
        int hb = idx >> 8, n = idx & 255;
        int gate = n >> 6, j = n & 63;
        int srow = gate * 512 + hb * 64 + j;
        g_bias[idx] = b_ih[srow] + b_hh[srow];
    }
    grid_sync();

    const int m0 = (bid & 15) * 128;
    const int hb = bid >> 4;
    if (bid < TILES) {
        for (int i = tid; i < 256; i += NTHR) biasS[i] = g_bias[hb * 256 + i];
    }

    const int b0 = (bid * BATCH) / NBLK;
    const int b1 = ((bid + 1) * BATCH) / NBLK;
    const int NR = b1 - b0;
    const float bout0 = b_out[0];

    // ---- MMA thread-geometry (8 warps, 64x64 warp tile) ----
    const int warp_m = warp & 1;          // 0/1 -> rows 0-63 / 64-127
    const int warp_n = warp >> 1;         // 0..3 -> 16-col slice within each gate
    const int l7 = lane & 7, q = lane >> 3;
    const int aRowL = warp_m * 64 + (q & 1) * 8 + l7;        // + mf*16
    const int cA    = q >> 1;
    const int bRowL = warp_n * 16 + (q >> 1) * 8 + l7;       // + gate*64
    const int cB    = q & 1;
    const int lq  = lane >> 2;
    const int lc2 = 2 * (lane & 3);

    for (int t = 0; t <= SEQ; ++t) {
        const int p = t & 1;
        // ================= ROW PHASE =================
        if (t == 0) {
            for (int b = b0 + warp; b < b1; b += 8) {
                for (int jj = lane; jj < HID; jj += 32) {
                    g_A[(size_t)b * AKC + 512 + jj] = __float2half_rn(h0[b * HID + jj]);
                    g_c[(size_t)b * HID + jj] = c0[b * HID + jj];
                }
            }
        } else if (t < SEQ && bid < TILES) {
            // prefetch first three h-half slabs (h(t) ready since last sync)
            issue_slab(sb,             8, m0, hb, tid, p); cp_commit();
            issue_slab(sb + STAGE,     9, m0, hb, tid, p); cp_commit();
            issue_slab(sb + 2 * STAGE, 10, m0, hb, tid, p); cp_commit();
        }
        // ---- y per row (sum of 8 epilogue partials), write out ----
        if (tid < NR) {
            const int b = b0 + tid;
            float yv;
            if (t == 0) {
                yv = y0[b];
            } else {
                float s = bout0;
                #pragma unroll
                for (int pp = 0; pp < 8; ++pp)
                    s += __ldcg(&g_ypart[(size_t)b * 8 + pp]);
                out[(size_t)(t - 1) * BATCH + b] = s;
                yv = s;
            }
            if (t < SEQ) inpS[tid * 32 + 31] = yv;
        }
        if (t == SEQ) break;

        // ---- stage x into inpS (smem-prefetched for MMA CTAs at t>0) ----
        if (t == 0 || bid >= TILES) {
            for (int i = tid; i < NR * 31; i += NTHR) {
                int r = i / 31, cc = i - r * 31;
                inpS[r * 32 + cc] = __ldcg(&x[((size_t)t * BATCH + (b0 + r)) * 31 + cc]);
            }
        }
        __syncthreads();

        // ---- col-block x0 GEMM: warp owns 64 cols, lane owns 2, all NR rows ----
        {
            const int jc = warp * 64 + lane * 2;
            const float2 bb = *(const float2*)(binS + jc);
            float2 ac[NRMAX];
            #pragma unroll
            for (int r = 0; r < NRMAX; ++r) ac[r] = bb;
            #pragma unroll 4
            for (int k = 0; k < 32; ++k) {
                const float2 w = *(const float2*)(g_WiT + k * HID + jc);
                #pragma unroll
                for (int r = 0; r < NRMAX; ++r) {
                    if (r < NR) {
                        const float a = inpS[r * 32 + k];
                        ac[r].x = fmaf(a, w.x, ac[r].x);
                        ac[r].y = fmaf(a, w.y, ac[r].y);
                    }
                }
            }
            #pragma unroll
            for (int r = 0; r < NRMAX; ++r) {
                if (r < NR) {
                    float vx = fmaxf(ac[r].x, 0.f), vy = fmaxf(ac[r].y, 0.f);
                    *(__half2*)(g_A + (size_t)(b0 + r) * AKC + jc) =
                        __floats2half2_rn(vx, vy);
                }
            }
        }

        grid_sync();   // A complete -> GEMM may read

        // ================= MMA PHASE (single-pass fp16, 4-stage pipeline) =======
        if (bid < TILES) {
            float acc[4][8][4];
            #pragma unroll
            for (int mf = 0; mf < 4; ++mf)
                #pragma unroll
                for (int nf = 0; nf < 8; ++nf)
                    #pragma unroll
                    for (int e = 0; e < 4; ++e) acc[mf][nf][e] = 0.f;

            if (t == 0) {   // no prefetch happened during row phase at t==0
                issue_slab(sb,             8, m0, hb, tid, p); cp_commit();
                issue_slab(sb + STAGE,     9, m0, hb, tid, p); cp_commit();
                issue_slab(sb + 2 * STAGE, 10, m0, hb, tid, p); cp_commit();
            }

            for (int i = 0; i < 16; ++i) {
                if (i <= 13) cp_wait2(); else if (i == 14) cp_wait1(); else cp_wait0();
                __syncthreads();     // slab i resident for ALL threads; buffer (i+3)&3 free
                if (i + 3 < 16) {
                    if (i == 0 && t + 1 < SEQ) {
                        // piggyback x(t+1) smem prefetch on this commit group
                        for (int ii = tid; ii < NR * 31; ii += NTHR) {
                            int r = ii / 31, cc = ii - r * 31;
                            cpasync4(smaddr(&inpS[r * 32 + cc]),
                                     &x[((size_t)(t + 1) * BATCH + (b0 + r)) * 31 + cc]);
                        }
                    }
                    issue_slab(sb + (uint32_t)((i + 3) & 3) * STAGE, kb_of(i + 3),
                               m0, hb, tid, p);
                    cp_commit();
                }
                const uint32_t bufb = sb + (uint32_t)(i & 3) * STAGE;
                #pragma unroll
                for (int s4i = 0; s4i < 4; ++s4i) {
                    const int s4 = (s4i + warp_n) & 3;   // dephase SMSP partners
                    uint32_t bh[4][4];
                    #pragma unroll
                    for (int g = 0; g < 4; ++g) {        // gate-major B frags
                        uint32_t baddr = bufb + OFF_B
                            + (uint32_t)((bRowL + g * 64) * 128)
                            + (uint32_t)((((2 * s4 + cB) ^ l7)) << 4);
                        ldmx4(bh[g], baddr);
                    }
                    #pragma unroll
                    for (int mf = 0; mf < 4; ++mf) {
                        uint32_t ah[4];
                        uint32_t aaddr = bufb + OFF_A
                            + (uint32_t)((aRowL + mf * 16) * 128)
                            + (uint32_t)((((2 * s4 + cA) ^ l7)) << 4);
                        ldmx4(ah, aaddr);
                        #pragma unroll
                        for (int nf = 0; nf < 8; ++nf)
                            mma16816(acc[mf][nf], ah, &bh[nf >> 1][(nf & 1) * 2]);
                    }
                }
            }

            // ---- register-resident LSTM epilogue (i,f,g,o all local) ----
            #pragma unroll
            for (int mf = 0; mf < 4; ++mf) {
                #pragma unroll
                for (int e2 = 0; e2 < 2; ++e2) {
                    const int r  = warp_m * 64 + mf * 16 + e2 * 8 + lq;
                    const int rg = m0 + r;
                    const int e0 = e2 * 2;
                    float yp = 0.f;
                    #pragma unroll
                    for (int sub = 0; sub < 2; ++sub) {
                        const int jl = warp_n * 16 + sub * 8 + lc2;   // 0..63
                        float I0 = sigap(acc[mf][0 + sub][e0]     + biasS[jl]);
                        float I1 = sigap(acc[mf][0 + sub][e0 + 1] + biasS[jl + 1]);
                        float F0 = sigap(acc[mf][2 + sub][e0]     + biasS[64 + jl]);
                        float F1 = sigap(acc[mf][2 + sub][e0 + 1] + biasS[64 + jl + 1]);
                        float G0 = tanhap(acc[mf][4 + sub][e0]     + biasS[128 + jl]);
                        float G1 = tanhap(acc[mf][4 + sub][e0 + 1] + biasS[128 + jl + 1]);
                        float O0 = sigap(acc[mf][6 + sub][e0]     + biasS[192 + jl]);
                        float O1 = sigap(acc[mf][6 + sub][e0 + 1] + biasS[192 + jl + 1]);
                        float* cp = g_c + (size_t)rg * HID + hb * 64 + jl;
                        float2 cv = *(float2*)cp;
                        float cn0 = F0 * cv.x + I0 * G0;
                        float cn1 = F1 * cv.y + I1 * G1;
                        *(float2*)cp = make_float2(cn0, cn1);
                        float h0f = O0 * tanhap(cn0);
                        float h1f = O1 * tanhap(cn1);
                        const float2 wv = *(const float2*)(woutS + hb * 64 + jl);
                        yp = fmaf(h0f, wv.x, fmaf(h1f, wv.y, yp));
                        // write h(t+1) into the OTHER h buffer (race-free)
                        *(__half2*)(g_A + (size_t)rg * AKC + 512 + (p ^ 1) * 512
                                    + hb * 64 + jl) = __floats2half2_rn(h0f, h1f);
                    }
                    yp += __shfl_xor_sync(0xffffffffu, yp, 1);
                    yp += __shfl_xor_sync(0xffffffffu, yp, 2);
                    if ((lane & 3) == 0) atomicAdd(&ypartS[r], yp);
                }
            }
            __syncthreads();
            if (tid < 128) {
                g_ypart[(size_t)(m0 + tid) * 8 + hb] = ypartS[tid];
                ypartS[tid] = 0.f;
            }
        }

        grid_sync();   // h + ypart complete -> next row phase may read
    }
}

extern "C" void kernel_launch(void* const* d_in, const int* in_sizes, int n_in,
                              void* d_out, int out_size) {
    (void)in_sizes; (void)n_in; (void)out_size;
    const float* x     = (const float*)d_in[0];
    const float* h0    = (const float*)d_in[1];
    const float* c0    = (const float*)d_in[2];
    const float* y0    = (const float*)d_in[3];
    const float* W_in  = (const float*)d_in[4];
    const float* b_in  = (const float*)d_in[5];
    const float* W_ih  = (const float*)d_in[6];
    const float* W_hh  = (const float*)d_in[7];
    const float* b_ih  = (const float*)d_in[8];
    const float* b_hh  = (const float*)d_in[9];
    const float* W_out = (const float*)d_in[10];
    const float* b_out = (const float*)d_in[11];
    float* out = (float*)d_out;

    cudaFuncSetAttribute(lstm_persist, cudaFuncAttributeMaxDynamicSharedMemorySize, DYNSMEM);
    lstm_persist<<<NBLK, NTHR, DYNSMEM>>>(x, h0, c0, y0, W_in, b_in, W_ih, W_hh,
                                          b_ih, b_hh, W_out, b_out, out);
}